// round 16
// baseline (speedup 1.0000x reference)
#include <cuda_runtime.h>
#include <cstdint>

#define N_PTS   32768
#define S_NBR   32
#define C_IN    64
#define C_OUT   128
#define NS      (N_PTS * S_NBR)   // 1048576
#define EPSBN   1e-5f

// Scratch (device globals; no allocation allowed)
__device__ float g_ypre[C_OUT * N_PTS];   // [o][n] 16 MB
__device__ float g_rpre[C_OUT * N_PTS];   // [o][n] 16 MB
__device__ float g_stats[4 * C_OUT];      // [sum_f | sumsq_f | sum_r | sumsq_r]

// ---- k_fused dynamic smem layout (float offsets) ----
// tile:  16 slots x 1024 floats = 16384 floats (65536 B)
//        phase 1: 4 pipeline stages x 4 channels x 4KB
//        phase 2/3: Ws (8192 floats) + bs (128) + pf tile (2048)
// aggs:  64*32 = 2048 floats
// wq:    64 float4 = 256 floats
// mbar:  4 x u64
#define AGGS_OFF   16384
#define WQ_OFF     (AGGS_OFF + 2048)          // 18432
#define MBAR_BYTE  ((WQ_OFF + 256) * 4)       // 74752
#define SMEM_BYTES (MBAR_BYTE + 32)           // 74784 -> 3 CTAs/SM

#define WS_OFF     0
#define BS_OFF     8192
#define PF_OFF     8320

// ---------------------------------------------------------------------------
__device__ __forceinline__ uint32_t smem_u32(const void* p) {
    uint32_t a;
    asm("{ .reg .u64 t; cvta.to.shared.u64 t, %1; cvt.u32.u64 %0, t; }"
        : "=r"(a) : "l"(p));
    return a;
}
__device__ __forceinline__ void bulk_g2s(uint32_t dst, const void* src,
                                         uint32_t bytes, uint32_t mbar) {
    asm volatile(
        "cp.async.bulk.shared::cta.global.mbarrier::complete_tx::bytes "
        "[%0], [%1], %2, [%3];"
        :: "r"(dst), "l"(src), "r"(bytes), "r"(mbar) : "memory");
}
__device__ __forceinline__ void mbar_init(uint32_t mbar, uint32_t cnt) {
    asm volatile("mbarrier.init.shared.b64 [%0], %1;" :: "r"(mbar), "r"(cnt) : "memory");
}
__device__ __forceinline__ void mbar_expect_tx(uint32_t mbar, uint32_t bytes) {
    asm volatile("mbarrier.arrive.expect_tx.shared.b64 _, [%0], %1;"
                 :: "r"(mbar), "r"(bytes) : "memory");
}
__device__ __forceinline__ void mbar_wait(uint32_t mbar, uint32_t parity) {
    asm volatile(
        "{\n\t.reg .pred P;\n\t"
        "W_%=:\n\t"
        "mbarrier.try_wait.parity.acquire.cta.shared::cta.b64 P, [%0], %1, 0x989680;\n\t"
        "@!P bra W_%=;\n\t}"
        :: "r"(mbar), "r"(parity) : "memory");
}

// ---------------------------------------------------------------------------
__global__ void k_zero_stats() {
    g_stats[threadIdx.x] = 0.0f;
}

// ---------------------------------------------------------------------------
// R14 fused kernel + inline BN statistics in the GEMV epilogues.
// Block = 256 threads, 32 points, ~74.8 KB smem -> 3 CTAs/SM.
// Phase 1: 16 chunks of 4 channels via 4-stage cp.async.bulk pipeline.
//   Warp owns 4 FIXED points (pt = 4*warp + (lane>>3)); s4 = lane&7.
//   Positions in 12 registers. Inner loop = 1 LDS.128 + 1 broadcast/channel.
// Phase 2: feature GEMV (warp = 16-output slab as 2x8) + stats atomics.
// Phase 3: residual GEMV (pf tile staged) + stats atomics.
__global__ __launch_bounds__(256) void k_fused(
    const float* __restrict__ xyz,     // [N][3]
    const float* __restrict__ np,      // [67][N][S]
    const float* __restrict__ pf,      // [64][N]
    const float* __restrict__ Wint,    // [64][3]
    const float* __restrict__ bint,    // [64]
    const float* __restrict__ Wfeat,   // [128][64]
    const float* __restrict__ bfeat,   // [128]
    const float* __restrict__ Wres,    // [128][64]
    const float* __restrict__ bres)    // [128]
{
    extern __shared__ __align__(16) float smf[];
    float*  tile = smf;                 // 16384 floats
    float*  aggs = smf + AGGS_OFF;      // [c][32]
    float4* wq   = (float4*)(smf + WQ_OFF);
    uint32_t smem_base = smem_u32(smf);
    uint32_t mbar0 = smem_base + MBAR_BYTE;

    int tid  = threadIdx.x;
    int warp = tid >> 5;
    int lane = tid & 31;
    int n0   = blockIdx.x * 32;

    // ---- init 4 barriers, issue chunks 0..3 (fills whole 64 KB tile) ----
    if (tid == 0) {
        #pragma unroll
        for (int b = 0; b < 4; b++) mbar_init(mbar0 + b * 8, 1);
        asm volatile("fence.proxy.async.shared::cta;" ::: "memory");
    }
    __syncthreads();
    if (tid == 0) {
        #pragma unroll
        for (int k = 0; k < 4; k++) {
            uint32_t mb = mbar0 + k * 8;
            mbar_expect_tx(mb, 16384u);
            const float* src = np + (size_t)(3 + k * 4) * NS + ((size_t)n0 << 5);
            #pragma unroll
            for (int cc = 0; cc < 4; cc++)
                bulk_g2s(smem_base + (uint32_t)(k * 4 + cc) * 4096u,
                         src + (size_t)cc * NS, 4096u, mb);
        }
    }

    // ---- stage wq (overlaps bulk copies) ----
    if (tid < C_IN)
        wq[tid] = make_float4(Wint[tid*3+0], Wint[tid*3+1], Wint[tid*3+2], bint[tid]);

    // ---- positions: loaded once into registers ----
    int s4  = lane & 7;
    int idx = lane >> 3;
    int pt  = (warp << 2) | idx;        // this thread's point (fixed)
    int n   = n0 + pt;
    float4 px, py, pz;
    {
        unsigned po = ((unsigned)n << 5) + ((unsigned)s4 << 2);
        px = *(const float4*)(np + 0u * NS + po);
        py = *(const float4*)(np + 1u * NS + po);
        pz = *(const float4*)(np + 2u * NS + po);
        float x0 = xyz[n*3+0], x1 = xyz[n*3+1], x2 = xyz[n*3+2];
        px.x -= x0; px.y -= x0; px.z -= x0; px.w -= x0;
        py.x -= x1; py.y -= x1; py.z -= x1; py.w -= x1;
        pz.x -= x2; pz.y -= x2; pz.z -= x2; pz.w -= x2;
    }
    __syncthreads();   // wq visible

    // ---- Phase 1: 16 chunks of 4 channels, 4-stage pipeline ----
    {
        const float4* tile4 = (const float4*)tile;
        #pragma unroll 1
        for (int k = 0; k < 16; k++) {
            int b  = k & 3;
            int ph = (k >> 2) & 1;
            mbar_wait(mbar0 + b * 8, (uint32_t)ph);

            #pragma unroll
            for (int ci = 0; ci < 4; ci++) {
                int c = k * 4 + ci;
                float4 w = wq[c];                                      // broadcast
                float4 f = tile4[(b * 4 + ci) * 256 + (pt << 3) + s4]; // 512B/warp

                float h0 = fmaf(w.x, px.x, fmaf(w.y, py.x, fmaf(w.z, pz.x, w.w)));
                float h1 = fmaf(w.x, px.y, fmaf(w.y, py.y, fmaf(w.z, pz.y, w.w)));
                float h2 = fmaf(w.x, px.z, fmaf(w.y, py.z, fmaf(w.z, pz.z, w.w)));
                float h3 = fmaf(w.x, px.w, fmaf(w.y, py.w, fmaf(w.z, pz.w, w.w)));

                float acc;
                acc = fmaxf(h0, 0.0f) * f.x;
                acc = fmaf(fmaxf(h1, 0.0f), f.y, acc);
                acc = fmaf(fmaxf(h2, 0.0f), f.z, acc);
                acc = fmaf(fmaxf(h3, 0.0f), f.w, acc);

                acc += __shfl_xor_sync(0xffffffffu, acc, 1);
                acc += __shfl_xor_sync(0xffffffffu, acc, 2);
                acc += __shfl_xor_sync(0xffffffffu, acc, 4);
                if (s4 == 0) aggs[c * 32 + pt] = acc;   // conflict-free
            }
            __syncthreads();                 // all warps done with buffer b

            if (tid == 0 && k < 12) {        // refill buffer b with chunk k+4
                int kn = k + 4;
                uint32_t mb = mbar0 + b * 8;
                mbar_expect_tx(mb, 16384u);
                const float* src = np + (size_t)(3 + kn * 4) * NS + ((size_t)n0 << 5);
                #pragma unroll
                for (int cc = 0; cc < 4; cc++)
                    bulk_g2s(smem_base + (uint32_t)(b * 4 + cc) * 4096u,
                             src + (size_t)cc * NS, 4096u, mb);
            }
        }
    }

    // ---- stage feature-path GEMV operands into the freed tile region ----
    {
        const float4* W4 = (const float4*)Wfeat;
        float4* Ws = (float4*)(tile + WS_OFF);
        #pragma unroll
        for (int i = tid; i < C_OUT * (C_IN/4); i += 256) Ws[i] = W4[i];
        if (tid < C_OUT) tile[BS_OFF + tid] = bfeat[tid];
    }
    __syncthreads();

    // ---- Phase 2: feature GEMV (two 8-output half-passes) + stats ----
    {
        const float4* Ws = (const float4*)(tile + WS_OFF);
        int nn = n0 + lane;
        #pragma unroll
        for (int half = 0; half < 2; half++) {
            int o0 = warp * 16 + half * 8;
            float acc[8];
            #pragma unroll
            for (int oi = 0; oi < 8; oi++) acc[oi] = tile[BS_OFF + o0 + oi];

            #pragma unroll 4
            for (int c4 = 0; c4 < C_IN/4; c4++) {
                float f0 = aggs[(c4*4+0) * 32 + lane];
                float f1 = aggs[(c4*4+1) * 32 + lane];
                float f2 = aggs[(c4*4+2) * 32 + lane];
                float f3 = aggs[(c4*4+3) * 32 + lane];
                #pragma unroll
                for (int oi = 0; oi < 8; oi++) {
                    float4 w4 = Ws[(o0 + oi) * (C_IN/4) + c4];
                    acc[oi] = fmaf(f0, w4.x, acc[oi]);
                    acc[oi] = fmaf(f1, w4.y, acc[oi]);
                    acc[oi] = fmaf(f2, w4.z, acc[oi]);
                    acc[oi] = fmaf(f3, w4.w, acc[oi]);
                }
            }
            #pragma unroll
            for (int oi = 0; oi < 8; oi++)
                g_ypre[(o0 + oi) * N_PTS + nn] = acc[oi];   // coalesced

            // inline BN stats: warp-reduce per output, one atomic per moment
            #pragma unroll
            for (int oi = 0; oi < 8; oi++) {
                float s1 = acc[oi];
                float s2 = acc[oi] * acc[oi];
                #pragma unroll
                for (int off = 16; off; off >>= 1) {
                    s1 += __shfl_xor_sync(0xffffffffu, s1, off);
                    s2 += __shfl_xor_sync(0xffffffffu, s2, off);
                }
                if (lane == 0) {
                    atomicAdd(&g_stats[o0 + oi], s1);
                    atomicAdd(&g_stats[C_OUT + o0 + oi], s2);
                }
            }
        }
    }
    __syncthreads();

    // ---- stage residual operands ----
    {
        const float4* W4 = (const float4*)Wres;
        float4* Ws = (float4*)(tile + WS_OFF);
        #pragma unroll
        for (int i = tid; i < C_OUT * (C_IN/4); i += 256) Ws[i] = W4[i];
        if (tid < C_OUT) tile[BS_OFF + tid] = bres[tid];
    }
    #pragma unroll
    for (int i = tid; i < C_IN * 32; i += 256) {
        int cc = i >> 5, col = i & 31;
        tile[PF_OFF + i] = pf[cc * N_PTS + n0 + col];   // coalesced
    }
    __syncthreads();

    // ---- Phase 3: residual GEMV + stats ----
    {
        const float4* Ws = (const float4*)(tile + WS_OFF);
        int nn = n0 + lane;
        #pragma unroll
        for (int half = 0; half < 2; half++) {
            int o0 = warp * 16 + half * 8;
            float acc[8];
            #pragma unroll
            for (int oi = 0; oi < 8; oi++) acc[oi] = tile[BS_OFF + o0 + oi];

            #pragma unroll 4
            for (int c4 = 0; c4 < C_IN/4; c4++) {
                float f0 = tile[PF_OFF + (c4*4+0) * 32 + lane];
                float f1 = tile[PF_OFF + (c4*4+1) * 32 + lane];
                float f2 = tile[PF_OFF + (c4*4+2) * 32 + lane];
                float f3 = tile[PF_OFF + (c4*4+3) * 32 + lane];
                #pragma unroll
                for (int oi = 0; oi < 8; oi++) {
                    float4 w4 = Ws[(o0 + oi) * (C_IN/4) + c4];
                    acc[oi] = fmaf(f0, w4.x, acc[oi]);
                    acc[oi] = fmaf(f1, w4.y, acc[oi]);
                    acc[oi] = fmaf(f2, w4.z, acc[oi]);
                    acc[oi] = fmaf(f3, w4.w, acc[oi]);
                }
            }
            #pragma unroll
            for (int oi = 0; oi < 8; oi++)
                g_rpre[(o0 + oi) * N_PTS + nn] = acc[oi];

            #pragma unroll
            for (int oi = 0; oi < 8; oi++) {
                float s1 = acc[oi];
                float s2 = acc[oi] * acc[oi];
                #pragma unroll
                for (int off = 16; off; off >>= 1) {
                    s1 += __shfl_xor_sync(0xffffffffu, s1, off);
                    s2 += __shfl_xor_sync(0xffffffffu, s2, off);
                }
                if (lane == 0) {
                    atomicAdd(&g_stats[2*C_OUT + o0 + oi], s1);
                    atomicAdd(&g_stats[3*C_OUT + o0 + oi], s2);
                }
            }
        }
    }
}

// ---------------------------------------------------------------------------
// Finalize: BN coefficients inline from g_stats, affine + ReLU both paths,
// add, float4 throughout.
__global__ __launch_bounds__(256) void k_final(
    const float* __restrict__ gf, const float* __restrict__ btf,
    const float* __restrict__ gr, const float* __restrict__ btr,
    float* __restrict__ out)
{
    int i4 = blockIdx.x * 256 + threadIdx.x;    // float4 index
    int o  = i4 >> 13;                          // channel
    const float inv = 1.0f / (float)N_PTS;

    float mf = g_stats[o] * inv;
    float vf = g_stats[C_OUT + o] * inv - mf * mf;
    float Af = gf[o] * rsqrtf(vf + EPSBN);
    float Bf = btf[o] - mf * Af;

    float mr = g_stats[2*C_OUT + o] * inv;
    float vr = g_stats[3*C_OUT + o] * inv - mr * mr;
    float Ar = gr[o] * rsqrtf(vr + EPSBN);
    float Br = btr[o] - mr * Ar;

    float4 y = ((const float4*)g_ypre)[i4];
    float4 r = ((const float4*)g_rpre)[i4];
    float4 v;
    v.x = fmaxf(fmaf(y.x, Af, Bf), 0.0f) + fmaxf(fmaf(r.x, Ar, Br), 0.0f);
    v.y = fmaxf(fmaf(y.y, Af, Bf), 0.0f) + fmaxf(fmaf(r.y, Ar, Br), 0.0f);
    v.z = fmaxf(fmaf(y.z, Af, Bf), 0.0f) + fmaxf(fmaf(r.z, Ar, Br), 0.0f);
    v.w = fmaxf(fmaf(y.w, Af, Bf), 0.0f) + fmaxf(fmaf(r.w, Ar, Br), 0.0f);
    ((float4*)out)[i4] = v;
}

// ---------------------------------------------------------------------------
extern "C" void kernel_launch(void* const* d_in, const int* in_sizes, int n_in,
                              void* d_out, int out_size) {
    const float* xyz   = (const float*)d_in[0];
    const float* pf    = (const float*)d_in[1];
    const float* np    = (const float*)d_in[2];
    const float* Wint  = (const float*)d_in[3];
    const float* bint  = (const float*)d_in[4];
    const float* Wfeat = (const float*)d_in[5];
    const float* bfeat = (const float*)d_in[6];
    const float* gfeat = (const float*)d_in[7];
    const float* befeat= (const float*)d_in[8];
    const float* Wres  = (const float*)d_in[9];
    const float* bres  = (const float*)d_in[10];
    const float* gres  = (const float*)d_in[11];
    const float* beres = (const float*)d_in[12];
    float* out = (float*)d_out;

    static bool attr_done = false;
    if (!attr_done) {
        cudaFuncSetAttribute(k_fused, cudaFuncAttributeMaxDynamicSharedMemorySize,
                             SMEM_BYTES);
        attr_done = true;
    }

    k_zero_stats<<<1, 4 * C_OUT>>>();
    k_fused<<<N_PTS / 32, 256, SMEM_BYTES>>>(xyz, np, pf, Wint, bint,
                                             Wfeat, bfeat, Wres, bres);
    k_final<<<(C_OUT * N_PTS / 4) / 256, 256>>>(gfeat, befeat, gres, beres, out);
}

// round 17
// speedup vs baseline: 1.6219x; 1.6219x over previous
#include <cuda_runtime.h>
#include <cstdint>

#define N_PTS   32768
#define S_NBR   32
#define C_IN    64
#define C_OUT   128
#define NS      (N_PTS * S_NBR)   // 1048576
#define EPSBN   1e-5f

// Scratch (device globals; no allocation allowed)
__device__ float  g_ypre[C_OUT * N_PTS];   // [o][n] 16 MB
__device__ float  g_rpre[C_OUT * N_PTS];   // [o][n] 16 MB
__device__ float2 g_part[2 * C_OUT * 4];   // partial (sum,sumsq) per (path,o,quarter)

// ---- k_fused dynamic smem layout (float offsets) ----
// tile:  16 slots x 1024 floats = 16384 floats (65536 B)
//        phase 1: 4 pipeline stages x 4 channels x 4KB
//        phase 2/3: Ws (8192 floats) + bs (128) + pf tile (2048)
// aggs:  64*32 = 2048 floats
// wq:    64 float4 = 256 floats
// mbar:  4 full + 4 empty (u64 each)
#define AGGS_OFF   16384
#define WQ_OFF     (AGGS_OFF + 2048)          // 18432
#define MBAR_BYTE  ((WQ_OFF + 256) * 4)       // 74752 (full[0..3] then empty[0..3])
#define SMEM_BYTES (MBAR_BYTE + 64)           // 74816 -> 3 CTAs/SM

#define WS_OFF     0
#define BS_OFF     8192
#define PF_OFF     8320

#define NTHREADS   288                         // 8 compute warps + 1 producer warp

// ---------------------------------------------------------------------------
__device__ __forceinline__ uint32_t smem_u32(const void* p) {
    uint32_t a;
    asm("{ .reg .u64 t; cvta.to.shared.u64 t, %1; cvt.u32.u64 %0, t; }"
        : "=r"(a) : "l"(p));
    return a;
}
__device__ __forceinline__ void bulk_g2s(uint32_t dst, const void* src,
                                         uint32_t bytes, uint32_t mbar) {
    asm volatile(
        "cp.async.bulk.shared::cta.global.mbarrier::complete_tx::bytes "
        "[%0], [%1], %2, [%3];"
        :: "r"(dst), "l"(src), "r"(bytes), "r"(mbar) : "memory");
}
__device__ __forceinline__ void mbar_init(uint32_t mbar, uint32_t cnt) {
    asm volatile("mbarrier.init.shared.b64 [%0], %1;" :: "r"(mbar), "r"(cnt) : "memory");
}
__device__ __forceinline__ void mbar_expect_tx(uint32_t mbar, uint32_t bytes) {
    asm volatile("mbarrier.arrive.expect_tx.shared.b64 _, [%0], %1;"
                 :: "r"(mbar), "r"(bytes) : "memory");
}
__device__ __forceinline__ void mbar_arrive(uint32_t mbar) {
    asm volatile("mbarrier.arrive.shared.b64 _, [%0];" :: "r"(mbar) : "memory");
}
__device__ __forceinline__ void mbar_wait(uint32_t mbar, uint32_t parity) {
    asm volatile(
        "{\n\t.reg .pred P;\n\t"
        "W_%=:\n\t"
        "mbarrier.try_wait.parity.acquire.cta.shared::cta.b64 P, [%0], %1, 0x989680;\n\t"
        "@!P bra W_%=;\n\t}"
        :: "r"(mbar), "r"(parity) : "memory");
}

// ---------------------------------------------------------------------------
// Warp-specialized fused kernel. 288 threads (8 compute warps + 1 producer),
// 32 points/block, ~74.8 KB smem -> 3 CTAs/SM.
// Phase 1: 16 chunks of 4 channels. Producer warp (thread 256) issues all
//   cp.async.bulk refills, gated by empty[] barriers (8 consumer-warp
//   arrivals). NO block-wide barriers inside the loop.
// Phase 2: feature GEMV (compute warps; warp = 16-output slab as 2x8).
// Phase 3: residual GEMV (pf tile staged).
__global__ __launch_bounds__(NTHREADS) void k_fused(
    const float* __restrict__ xyz,     // [N][3]
    const float* __restrict__ np,      // [67][N][S]
    const float* __restrict__ pf,      // [64][N]
    const float* __restrict__ Wint,    // [64][3]
    const float* __restrict__ bint,    // [64]
    const float* __restrict__ Wfeat,   // [128][64]
    const float* __restrict__ bfeat,   // [128]
    const float* __restrict__ Wres,    // [128][64]
    const float* __restrict__ bres)    // [128]
{
    extern __shared__ __align__(16) float smf[];
    float*  tile = smf;                 // 16384 floats
    float*  aggs = smf + AGGS_OFF;      // [c][32]
    float4* wq   = (float4*)(smf + WQ_OFF);
    uint32_t smem_base = smem_u32(smf);
    uint32_t full0  = smem_base + MBAR_BYTE;        // full[b]  = full0 + 8b
    uint32_t empty0 = smem_base + MBAR_BYTE + 32;   // empty[b] = empty0 + 8b

    int tid  = threadIdx.x;
    int warp = tid >> 5;
    int lane = tid & 31;
    int n0   = blockIdx.x * 32;

    // ---- init barriers ----
    if (tid == 0) {
        #pragma unroll
        for (int b = 0; b < 4; b++) {
            mbar_init(full0  + b * 8, 1);   // completed by TMA tx bytes
            mbar_init(empty0 + b * 8, 8);   // one arrival per compute warp
        }
        asm volatile("fence.proxy.async.shared::cta;" ::: "memory");
    }
    __syncthreads();

    // ---- stage wq ----
    if (tid < C_IN)
        wq[tid] = make_float4(Wint[tid*3+0], Wint[tid*3+1], Wint[tid*3+2], bint[tid]);

    // ---- prologue: producer issues chunks 0..3 (fills 64 KB tile) ----
    if (tid == 256) {
        #pragma unroll
        for (int k = 0; k < 4; k++) {
            uint32_t mb = full0 + k * 8;
            mbar_expect_tx(mb, 16384u);
            const float* src = np + (size_t)(3 + k * 4) * NS + ((size_t)n0 << 5);
            #pragma unroll
            for (int cc = 0; cc < 4; cc++)
                bulk_g2s(smem_base + (uint32_t)(k * 4 + cc) * 4096u,
                         src + (size_t)cc * NS, 4096u, mb);
        }
    }

    // ---- positions: compute warps load once into registers ----
    int s4  = lane & 7;
    int idx = lane >> 3;
    int pt  = (warp << 2) | idx;        // fixed point (compute warps)
    float4 px = {}, py = {}, pz = {};
    if (warp < 8) {
        int n = n0 + pt;
        unsigned po = ((unsigned)n << 5) + ((unsigned)s4 << 2);
        px = *(const float4*)(np + 0u * NS + po);
        py = *(const float4*)(np + 1u * NS + po);
        pz = *(const float4*)(np + 2u * NS + po);
        float x0 = xyz[n*3+0], x1 = xyz[n*3+1], x2 = xyz[n*3+2];
        px.x -= x0; px.y -= x0; px.z -= x0; px.w -= x0;
        py.x -= x1; py.y -= x1; py.z -= x1; py.w -= x1;
        pz.x -= x2; pz.y -= x2; pz.z -= x2; pz.w -= x2;
    }
    __syncthreads();   // wq visible to all

    // ---- Phase 1: producer / consumer loop (no block barriers) ----
    if (warp < 8) {
        const float4* tile4 = (const float4*)tile;
        #pragma unroll 1
        for (int k = 0; k < 16; k++) {
            int b  = k & 3;
            int ph = (k >> 2) & 1;
            mbar_wait(full0 + b * 8, (uint32_t)ph);

            #pragma unroll
            for (int ci = 0; ci < 4; ci++) {
                int c = k * 4 + ci;
                float4 w = wq[c];                                      // broadcast
                float4 f = tile4[(b * 4 + ci) * 256 + (pt << 3) + s4]; // 512B/warp

                float h0 = fmaf(w.x, px.x, fmaf(w.y, py.x, fmaf(w.z, pz.x, w.w)));
                float h1 = fmaf(w.x, px.y, fmaf(w.y, py.y, fmaf(w.z, pz.y, w.w)));
                float h2 = fmaf(w.x, px.z, fmaf(w.y, py.z, fmaf(w.z, pz.z, w.w)));
                float h3 = fmaf(w.x, px.w, fmaf(w.y, py.w, fmaf(w.z, pz.w, w.w)));

                float acc;
                acc = fmaxf(h0, 0.0f) * f.x;
                acc = fmaf(fmaxf(h1, 0.0f), f.y, acc);
                acc = fmaf(fmaxf(h2, 0.0f), f.z, acc);
                acc = fmaf(fmaxf(h3, 0.0f), f.w, acc);

                acc += __shfl_xor_sync(0xffffffffu, acc, 1);
                acc += __shfl_xor_sync(0xffffffffu, acc, 2);
                acc += __shfl_xor_sync(0xffffffffu, acc, 4);
                if (s4 == 0) aggs[c * 32 + pt] = acc;   // conflict-free
            }
            if (lane == 0) mbar_arrive(empty0 + b * 8);  // this warp done with b
        }
    } else if (tid == 256) {
        // producer: refill chunk kn into buffer kn&3 once its previous
        // occupant (chunk kn-4) has been consumed by all 8 warps.
        #pragma unroll 1
        for (int kn = 4; kn < 16; kn++) {
            int b = kn & 3;
            int g = (kn - 4) >> 2;                 // empty generation
            mbar_wait(empty0 + b * 8, (uint32_t)(g & 1));
            uint32_t mb = full0 + b * 8;
            mbar_expect_tx(mb, 16384u);
            const float* src = np + (size_t)(3 + kn * 4) * NS + ((size_t)n0 << 5);
            #pragma unroll
            for (int cc = 0; cc < 4; cc++)
                bulk_g2s(smem_base + (uint32_t)(b * 4 + cc) * 4096u,
                         src + (size_t)cc * NS, 4096u, mb);
        }
    }
    __syncthreads();   // aggs complete; tile free for reuse

    // ---- stage feature-path GEMV operands into the freed tile region ----
    {
        const float4* W4 = (const float4*)Wfeat;
        float4* Ws = (float4*)(tile + WS_OFF);
        #pragma unroll
        for (int i = tid; i < C_OUT * (C_IN/4); i += NTHREADS) Ws[i] = W4[i];
        if (tid < C_OUT) tile[BS_OFF + tid] = bfeat[tid];
    }
    __syncthreads();

    // ---- Phase 2: feature GEMV (two 8-output half-passes) ----
    if (warp < 8) {
        const float4* Ws = (const float4*)(tile + WS_OFF);
        int nn = n0 + lane;
        #pragma unroll
        for (int half = 0; half < 2; half++) {
            int o0 = warp * 16 + half * 8;
            float acc[8];
            #pragma unroll
            for (int oi = 0; oi < 8; oi++) acc[oi] = tile[BS_OFF + o0 + oi];

            #pragma unroll 4
            for (int c4 = 0; c4 < C_IN/4; c4++) {
                float f0 = aggs[(c4*4+0) * 32 + lane];
                float f1 = aggs[(c4*4+1) * 32 + lane];
                float f2 = aggs[(c4*4+2) * 32 + lane];
                float f3 = aggs[(c4*4+3) * 32 + lane];
                #pragma unroll
                for (int oi = 0; oi < 8; oi++) {
                    float4 w4 = Ws[(o0 + oi) * (C_IN/4) + c4];
                    acc[oi] = fmaf(f0, w4.x, acc[oi]);
                    acc[oi] = fmaf(f1, w4.y, acc[oi]);
                    acc[oi] = fmaf(f2, w4.z, acc[oi]);
                    acc[oi] = fmaf(f3, w4.w, acc[oi]);
                }
            }
            #pragma unroll
            for (int oi = 0; oi < 8; oi++)
                g_ypre[(o0 + oi) * N_PTS + nn] = acc[oi];   // coalesced
        }
    }
    __syncthreads();

    // ---- stage residual operands ----
    {
        const float4* W4 = (const float4*)Wres;
        float4* Ws = (float4*)(tile + WS_OFF);
        #pragma unroll
        for (int i = tid; i < C_OUT * (C_IN/4); i += NTHREADS) Ws[i] = W4[i];
        if (tid < C_OUT) tile[BS_OFF + tid] = bres[tid];
    }
    #pragma unroll
    for (int i = tid; i < C_IN * 32; i += NTHREADS) {
        int cc = i >> 5, col = i & 31;
        tile[PF_OFF + i] = pf[cc * N_PTS + n0 + col];   // coalesced
    }
    __syncthreads();

    // ---- Phase 3: residual GEMV ----
    if (warp < 8) {
        const float4* Ws = (const float4*)(tile + WS_OFF);
        int nn = n0 + lane;
        #pragma unroll
        for (int half = 0; half < 2; half++) {
            int o0 = warp * 16 + half * 8;
            float acc[8];
            #pragma unroll
            for (int oi = 0; oi < 8; oi++) acc[oi] = tile[BS_OFF + o0 + oi];

            #pragma unroll 4
            for (int c4 = 0; c4 < C_IN/4; c4++) {
                float f0 = tile[PF_OFF + (c4*4+0) * 32 + lane];
                float f1 = tile[PF_OFF + (c4*4+1) * 32 + lane];
                float f2 = tile[PF_OFF + (c4*4+2) * 32 + lane];
                float f3 = tile[PF_OFF + (c4*4+3) * 32 + lane];
                #pragma unroll
                for (int oi = 0; oi < 8; oi++) {
                    float4 w4 = Ws[(o0 + oi) * (C_IN/4) + c4];
                    acc[oi] = fmaf(f0, w4.x, acc[oi]);
                    acc[oi] = fmaf(f1, w4.y, acc[oi]);
                    acc[oi] = fmaf(f2, w4.z, acc[oi]);
                    acc[oi] = fmaf(f3, w4.w, acc[oi]);
                }
            }
            #pragma unroll
            for (int oi = 0; oi < 8; oi++)
                g_rpre[(o0 + oi) * N_PTS + nn] = acc[oi];
        }
    }
}

// ---------------------------------------------------------------------------
// BN partial stats: 1024 blocks = (path, channel, quarter-row). No atomics.
__global__ __launch_bounds__(256) void k_stats(void)
{
    __shared__ float ws1[8], ws2[8];

    int bid  = blockIdx.x;
    int q    = bid & 3;
    int o    = (bid >> 2) & (C_OUT - 1);
    int path = bid >> 9;
    int tid  = threadIdx.x;

    const float4* src = (const float4*)((path ? g_rpre : g_ypre) + o * N_PTS)
                      + q * (N_PTS / 16);

    float s1 = 0.0f, s2 = 0.0f;
    #pragma unroll
    for (int i = tid; i < N_PTS/16; i += 256) {
        float4 v = src[i];
        s1 += v.x + v.y + v.z + v.w;
        s2 += v.x*v.x + v.y*v.y + v.z*v.z + v.w*v.w;
    }
    #pragma unroll
    for (int off = 16; off; off >>= 1) {
        s1 += __shfl_xor_sync(0xffffffffu, s1, off);
        s2 += __shfl_xor_sync(0xffffffffu, s2, off);
    }
    int warp = tid >> 5, lane = tid & 31;
    if (lane == 0) { ws1[warp] = s1; ws2[warp] = s2; }
    __syncthreads();
    if (tid == 0) {
        float t1 = 0.0f, t2 = 0.0f;
        #pragma unroll
        for (int w = 0; w < 8; w++) { t1 += ws1[w]; t2 += ws2[w]; }
        g_part[bid] = make_float2(t1, t2);
    }
}

// ---------------------------------------------------------------------------
// Finalize: reduce partials + BN coefficients inline, affine + ReLU both
// paths, add, float4 throughout.
__global__ __launch_bounds__(256) void k_final(
    const float* __restrict__ gf, const float* __restrict__ btf,
    const float* __restrict__ gr, const float* __restrict__ btr,
    float* __restrict__ out)
{
    int i4 = blockIdx.x * 256 + threadIdx.x;    // float4 index
    int o  = i4 >> 13;                          // channel
    const float inv = 1.0f / (float)N_PTS;

    float s1f = 0.0f, s2f = 0.0f, s1r = 0.0f, s2r = 0.0f;
    #pragma unroll
    for (int q = 0; q < 4; q++) {
        float2 pF = g_part[(o << 2) + q];
        float2 pR = g_part[(1 << 9) + (o << 2) + q];
        s1f += pF.x; s2f += pF.y;
        s1r += pR.x; s2r += pR.y;
    }

    float mf = s1f * inv;
    float vf = s2f * inv - mf * mf;
    float Af = gf[o] * rsqrtf(vf + EPSBN);
    float Bf = btf[o] - mf * Af;

    float mr = s1r * inv;
    float vr = s2r * inv - mr * mr;
    float Ar = gr[o] * rsqrtf(vr + EPSBN);
    float Br = btr[o] - mr * Ar;

    float4 y = ((const float4*)g_ypre)[i4];
    float4 r = ((const float4*)g_rpre)[i4];
    float4 v;
    v.x = fmaxf(fmaf(y.x, Af, Bf), 0.0f) + fmaxf(fmaf(r.x, Ar, Br), 0.0f);
    v.y = fmaxf(fmaf(y.y, Af, Bf), 0.0f) + fmaxf(fmaf(r.y, Ar, Br), 0.0f);
    v.z = fmaxf(fmaf(y.z, Af, Bf), 0.0f) + fmaxf(fmaf(r.z, Ar, Br), 0.0f);
    v.w = fmaxf(fmaf(y.w, Af, Bf), 0.0f) + fmaxf(fmaf(r.w, Ar, Br), 0.0f);
    ((float4*)out)[i4] = v;
}

// ---------------------------------------------------------------------------
extern "C" void kernel_launch(void* const* d_in, const int* in_sizes, int n_in,
                              void* d_out, int out_size) {
    const float* xyz   = (const float*)d_in[0];
    const float* pf    = (const float*)d_in[1];
    const float* np    = (const float*)d_in[2];
    const float* Wint  = (const float*)d_in[3];
    const float* bint  = (const float*)d_in[4];
    const float* Wfeat = (const float*)d_in[5];
    const float* bfeat = (const float*)d_in[6];
    const float* gfeat = (const float*)d_in[7];
    const float* befeat= (const float*)d_in[8];
    const float* Wres  = (const float*)d_in[9];
    const float* bres  = (const float*)d_in[10];
    const float* gres  = (const float*)d_in[11];
    const float* beres = (const float*)d_in[12];
    float* out = (float*)d_out;

    static bool attr_done = false;
    if (!attr_done) {
        cudaFuncSetAttribute(k_fused, cudaFuncAttributeMaxDynamicSharedMemorySize,
                             SMEM_BYTES);
        attr_done = true;
    }

    k_fused<<<N_PTS / 32, NTHREADS, SMEM_BYTES>>>(xyz, np, pf, Wint, bint,
                                                  Wfeat, bfeat, Wres, bres);
    k_stats<<<2 * C_OUT * 4, 256>>>();
    k_final<<<(C_OUT * N_PTS / 4) / 256, 256>>>(gfeat, befeat, gres, beres, out);
}